// round 3
// baseline (speedup 1.0000x reference)
#include <cuda_runtime.h>
#include <cstdint>

// Problem constants
#define BB 32
#define NN 1024
#define DD 512
#define KK 64
#define EPSF 1e-12f

// ---------------- scratch (static device arrays; no cudaMalloc) --------------
__device__ float g_P[BB * NN * KK];        // softmax probs [B,N,K]
__device__ float g_vlad[BB * KK * DD];     // raw vlad [B,K,D]
__device__ float g_asum[BB * KK];          // a_sum [B,K]
__device__ float g_rs[BB * KK];            // per-(b,k) intra-norm scale
__device__ float g_gn[BB];                 // per-b global sum of squares
__device__ float g_c2t[KK * DD];           // clusters2 transposed [K,D]

// ---------------- packed f32x2 helpers (Blackwell) ---------------------------
__device__ __forceinline__ void fma2(unsigned long long& d,
                                     unsigned long long a,
                                     unsigned long long b) {
    asm("fma.rn.f32x2 %0, %1, %2, %0;" : "+l"(d) : "l"(a), "l"(b));
}

// ---------------- kernel 0: transpose c2 [D,K] -> c2t [K,D] ------------------
__global__ void k_tc2(const float* __restrict__ c2, float* __restrict__ c2t) {
    __shared__ float t[32][33];
    int dt = blockIdx.x;   // 0..15
    int kt = blockIdx.y;   // 0..1
    int tx = threadIdx.x, ty = threadIdx.y;
#pragma unroll
    for (int r = 0; r < 4; r++) {
        int d = dt * 32 + ty + 8 * r;
        int k = kt * 32 + tx;
        t[ty + 8 * r][tx] = c2[d * KK + k];
    }
    __syncthreads();
#pragma unroll
    for (int r = 0; r < 4; r++) {
        int k = kt * 32 + ty + 8 * r;
        int d = dt * 32 + tx;
        c2t[k * DD + d] = t[tx][ty + 8 * r];
    }
}

// ---------------- kernel 1: softmax over K + a_sum ---------------------------
__global__ void __launch_bounds__(256) k_softmax(const float* __restrict__ bn,
                                                 float* __restrict__ P,
                                                 float* __restrict__ asum) {
    __shared__ float sAcc[KK];
    int tid = threadIdx.x;
    int w = tid >> 5;
    int lane = tid & 31;
    int row = blockIdx.x * 8 + w;          // 0..32767
    if (tid < KK) sAcc[tid] = 0.f;
    __syncthreads();

    const float* r = bn + (size_t)row * KK;
    float v0 = r[lane];
    float v1 = r[lane + 32];
    float m = fmaxf(v0, v1);
#pragma unroll
    for (int o = 16; o; o >>= 1) m = fmaxf(m, __shfl_xor_sync(0xffffffffu, m, o));
    float e0 = __expf(v0 - m);
    float e1 = __expf(v1 - m);
    float s = e0 + e1;
#pragma unroll
    for (int o = 16; o; o >>= 1) s += __shfl_xor_sync(0xffffffffu, s, o);
    float inv = 1.f / s;
    float p0 = e0 * inv;
    float p1 = e1 * inv;
    P[(size_t)row * KK + lane] = p0;
    P[(size_t)row * KK + lane + 32] = p1;
    atomicAdd(&sAcc[lane], p0);
    atomicAdd(&sAcc[lane + 32], p1);
    __syncthreads();
    if (tid < KK) atomicAdd(&asum[(blockIdx.x >> 7) * KK + tid], sAcc[tid]);
}

// ---------------- kernel 2: vlad[b,k,d] = sum_n P[b,n,k] * x[b,n,d] ----------
// grid (B, D/64); block 128 = 16(ty:k-groups of 4) x 8(tx:d-groups of 8)
// smem: duplicated P pairs (kills broadcast packs), x pairs loaded as u64x2.
#define DT 64
#define NC 32
__global__ void __launch_bounds__(128, 4) k_gemm(const float* __restrict__ Pg,
                                                 const float* __restrict__ xg,
                                                 float* __restrict__ vlad) {
    __shared__ float2 sP2[NC][KK];   // 16 KB : (p,p) duplicated pairs
    __shared__ float sX[NC][DT];     // 8 KB
    const int tid = threadIdx.x;
    const int tx = tid & 7;          // d group: 8 groups x 8 d
    const int ty = tid >> 3;         // k group: 16 groups x 4 k
    const int b = blockIdx.x;
    const int d0 = blockIdx.y * DT;
    const int bN = b * NN;

    unsigned long long acc[4][4];
#pragma unroll
    for (int i = 0; i < 4; i++)
#pragma unroll
        for (int j = 0; j < 4; j++) acc[i][j] = 0ull;

    float4 rp[4], rx[4];

    // prefetch chunk 0  (P chunk: 32x64 floats; X chunk: 32x64 floats)
#pragma unroll
    for (int j = 0; j < 4; j++) {
        int f = j * 128 + tid;
        int row = f >> 4, c = (f & 15) << 2;
        rp[j] = *(const float4*)&Pg[(((size_t)(bN + row)) << 6) + c];
        rx[j] = *(const float4*)&xg[(((size_t)(bN + row)) << 9) + d0 + c];
    }

    for (int n0 = 0; n0 < NN; n0 += NC) {
        __syncthreads();
#pragma unroll
        for (int j = 0; j < 4; j++) {
            int f = j * 128 + tid;
            int row = f >> 4, c = (f & 15) << 2;
            // duplicated P store: (x,x),(y,y) and (z,z),(w,w)
            float4 v = rp[j];
            *(float4*)&sP2[row][c]     = make_float4(v.x, v.x, v.y, v.y);
            *(float4*)&sP2[row][c + 2] = make_float4(v.z, v.z, v.w, v.w);
            *(float4*)&sX[row][c] = rx[j];
        }
        __syncthreads();

        if (n0 + NC < NN) {  // prefetch next chunk while computing
            int nn = n0 + NC;
#pragma unroll
            for (int j = 0; j < 4; j++) {
                int f = j * 128 + tid;
                int row = f >> 4, c = (f & 15) << 2;
                rp[j] = *(const float4*)&Pg[(((size_t)(bN + nn + row)) << 6) + c];
                rx[j] = *(const float4*)&xg[(((size_t)(bN + nn + row)) << 9) + d0 + c];
            }
        }

#pragma unroll
        for (int i = 0; i < NC; i++) {
            ulonglong2 pA = *(const ulonglong2*)&sP2[i][ty << 2];
            ulonglong2 pB = *(const ulonglong2*)&sP2[i][(ty << 2) + 2];
            ulonglong2 xA = *(const ulonglong2*)&sX[i][tx << 3];
            ulonglong2 xB = *(const ulonglong2*)&sX[i][(tx << 3) + 4];
            fma2(acc[0][0], pA.x, xA.x);
            fma2(acc[0][1], pA.x, xA.y);
            fma2(acc[0][2], pA.x, xB.x);
            fma2(acc[0][3], pA.x, xB.y);
            fma2(acc[1][0], pA.y, xA.x);
            fma2(acc[1][1], pA.y, xA.y);
            fma2(acc[1][2], pA.y, xB.x);
            fma2(acc[1][3], pA.y, xB.y);
            fma2(acc[2][0], pB.x, xA.x);
            fma2(acc[2][1], pB.x, xA.y);
            fma2(acc[2][2], pB.x, xB.x);
            fma2(acc[2][3], pB.x, xB.y);
            fma2(acc[3][0], pB.y, xA.x);
            fma2(acc[3][1], pB.y, xA.y);
            fma2(acc[3][2], pB.y, xB.x);
            fma2(acc[3][3], pB.y, xB.y);
        }
    }

    // write out tile: thread owns k = ty*4+kk, d = d0 + tx*8 .. +7
#pragma unroll
    for (int kk = 0; kk < 4; kk++) {
        size_t base = ((size_t)(b * KK + (ty << 2) + kk)) * DD + d0 + (tx << 3);
        *(ulonglong2*)&vlad[base]     = make_ulonglong2(acc[kk][0], acc[kk][1]);
        *(ulonglong2*)&vlad[base + 4] = make_ulonglong2(acc[kk][2], acc[kk][3]);
    }
}

// ---------------- kernel 3: per-(b,k) residual sumsq -> scale, global sumsq --
__global__ void __launch_bounds__(128) k_rowstat(const float* __restrict__ vlad,
                                                 const float* __restrict__ asum,
                                                 const float* __restrict__ c2t,
                                                 float* __restrict__ rs,
                                                 float* __restrict__ gn) {
    int bk = blockIdx.x;        // b*64 + k
    int b = bk >> 6;
    int k = bk & 63;
    float a = asum[bk];
    const float* vr = vlad + (size_t)bk * DD;
    const float* cr = c2t + (size_t)k * DD;
    float ss = 0.f;
#pragma unroll
    for (int j = threadIdx.x; j < DD; j += 128) {
        float v = vr[j] - a * cr[j];
        ss += v * v;
    }
#pragma unroll
    for (int o = 16; o; o >>= 1) ss += __shfl_xor_sync(0xffffffffu, ss, o);
    __shared__ float sw[4];
    if ((threadIdx.x & 31) == 0) sw[threadIdx.x >> 5] = ss;
    __syncthreads();
    if (threadIdx.x == 0) {
        float t = sw[0] + sw[1] + sw[2] + sw[3];
        float sc = rsqrtf(t + EPSF);
        rs[bk] = sc;
        atomicAdd(&gn[b], t * sc * sc);
    }
}

// ---------------- kernel 4: normalize + transpose [B,K,D] -> [B, D*K] --------
__global__ void k_final(const float* __restrict__ vlad,
                        const float* __restrict__ asum,
                        const float* __restrict__ c2t,
                        const float* __restrict__ rs,
                        const float* __restrict__ gn,
                        float* __restrict__ out) {
    int b = blockIdx.x;
    int dt = blockIdx.y;     // 0..15
    int kt = blockIdx.z;     // 0..1
    __shared__ float t[32][33];
    int tx = threadIdx.x;    // 0..31
    int ty = threadIdx.y;    // 0..7
#pragma unroll
    for (int r = 0; r < 4; r++) {
        int kl = ty + 8 * r;
        int k = kt * 32 + kl;
        int d = dt * 32 + tx;
        int bk = b * KK + k;
        float v = (vlad[(size_t)bk * DD + d] - asum[bk] * c2t[(size_t)k * DD + d]) * rs[bk];
        t[kl][tx] = v;
    }
    __syncthreads();
    float g = rsqrtf(gn[b] + EPSF);
#pragma unroll
    for (int r = 0; r < 4; r++) {
        int dl = ty + 8 * r;
        int d = dt * 32 + dl;
        int k = kt * 32 + tx;
        out[(size_t)b * (DD * KK) + d * KK + k] = t[tx][dl] * g;
    }
}

// ---------------- launcher ---------------------------------------------------
extern "C" void kernel_launch(void* const* d_in, const int* in_sizes, int n_in,
                              void* d_out, int out_size) {
    const float* x = (const float*)d_in[0];     // [B,N,D]
    const float* bn = (const float*)d_in[1];    // [B*N,K]
    const float* c2 = (const float*)d_in[2];    // [1,D,K]
    float* out = (float*)d_out;

    float *Pp, *vlad, *asum, *rs, *gn, *c2t;
    cudaGetSymbolAddress((void**)&Pp, g_P);
    cudaGetSymbolAddress((void**)&vlad, g_vlad);
    cudaGetSymbolAddress((void**)&asum, g_asum);
    cudaGetSymbolAddress((void**)&rs, g_rs);
    cudaGetSymbolAddress((void**)&gn, g_gn);
    cudaGetSymbolAddress((void**)&c2t, g_c2t);

    cudaMemsetAsync(asum, 0, BB * KK * sizeof(float));
    cudaMemsetAsync(gn, 0, BB * sizeof(float));

    k_tc2<<<dim3(DD / 32, KK / 32), dim3(32, 8)>>>(c2, c2t);
    k_softmax<<<(BB * NN) / 8, 256>>>(bn, Pp, asum);
    k_gemm<<<dim3(BB, DD / DT), 128>>>(Pp, x, vlad);
    k_rowstat<<<BB * KK, 128>>>(vlad, asum, c2t, rs, gn);
    k_final<<<dim3(BB, DD / 32, KK / 32), dim3(32, 8)>>>(vlad, asum, c2t, rs, gn, out);
}

// round 5
// speedup vs baseline: 1.7253x; 1.7253x over previous
#include <cuda_runtime.h>
#include <cstdint>

#define BB 32
#define NN 1024
#define DD 512
#define KK 64
#define EPSF 1e-12f

// ---------------- scratch ----------------------------------------------------
__device__ float g_Pt[BB * KK * NN];       // P transposed [B,K,N]
__device__ float g_vlad[BB * KK * DD];     // residual vlad' [B,K,D]
__device__ float g_asum[BB * KK];
__device__ float g_ss[BB * KK];            // per-(b,k) sumsq of residual
__device__ float g_rs[BB * KK];            // per-(b,k) rsqrt scale
__device__ float g_gn[BB];                 // per-b global rsqrt scale
__device__ float g_c2t[KK * DD];

// ---------------- helpers ----------------------------------------------------
__device__ __forceinline__ uint32_t tf32cvt(float f) {
    uint32_t u;
    asm("cvt.rna.tf32.f32 %0, %1;" : "=r"(u) : "f"(f));
    return u;
}
__device__ __forceinline__ void mma_tf32(float* c, const uint32_t* a, const uint32_t* b) {
    asm volatile(
        "mma.sync.aligned.m16n8k8.row.col.f32.tf32.tf32.f32 "
        "{%0,%1,%2,%3}, {%4,%5,%6,%7}, {%8,%9}, {%0,%1,%2,%3};"
        : "+f"(c[0]), "+f"(c[1]), "+f"(c[2]), "+f"(c[3])
        : "r"(a[0]), "r"(a[1]), "r"(a[2]), "r"(a[3]), "r"(b[0]), "r"(b[1]));
}

// ---------------- kernel 0: transpose c2 [D,K] -> c2t [K,D] ------------------
__global__ void k_tc2(const float* __restrict__ c2, float* __restrict__ c2t) {
    __shared__ float t[32][33];
    int dt = blockIdx.x, kt = blockIdx.y;
    int tx = threadIdx.x, ty = threadIdx.y;
#pragma unroll
    for (int r = 0; r < 4; r++)
        t[ty + 8 * r][tx] = c2[(dt * 32 + ty + 8 * r) * KK + kt * 32 + tx];
    __syncthreads();
#pragma unroll
    for (int r = 0; r < 4; r++)
        c2t[(kt * 32 + ty + 8 * r) * DD + dt * 32 + tx] = t[tx][ty + 8 * r];
}

// ---------------- kernel 1: softmax over K, write Pt [B,K,N], a_sum ----------
__global__ void __launch_bounds__(256) k_softmax(const float* __restrict__ bn,
                                                 float* __restrict__ Pt,
                                                 float* __restrict__ asum) {
    __shared__ float sp[32][65];
    __shared__ float sAcc[KK];
    int tid = threadIdx.x;
    int w = tid >> 5, lane = tid & 31;
    int blk = blockIdx.x;
    int b = blk >> 5;
    int n0 = (blk & 31) * 32;
    if (tid < KK) sAcc[tid] = 0.f;
    __syncthreads();

#pragma unroll
    for (int r = 0; r < 4; r++) {
        int nl = w * 4 + r;
        const float* row = bn + ((size_t)(b * NN + n0 + nl)) * KK;
        float v0 = row[lane], v1 = row[lane + 32];
        float m = fmaxf(v0, v1);
#pragma unroll
        for (int o = 16; o; o >>= 1) m = fmaxf(m, __shfl_xor_sync(0xffffffffu, m, o));
        float e0 = __expf(v0 - m), e1 = __expf(v1 - m);
        float s = e0 + e1;
#pragma unroll
        for (int o = 16; o; o >>= 1) s += __shfl_xor_sync(0xffffffffu, s, o);
        float inv = 1.f / s;
        float p0 = e0 * inv, p1 = e1 * inv;
        sp[nl][lane] = p0;
        sp[nl][lane + 32] = p1;
        atomicAdd(&sAcc[lane], p0);
        atomicAdd(&sAcc[lane + 32], p1);
    }
    __syncthreads();
#pragma unroll
    for (int rep = 0; rep < 8; rep++) {
        int k = rep * 8 + w;
        Pt[((size_t)(b * KK + k)) * NN + n0 + lane] = sp[lane][k];
    }
    if (tid < KK) atomicAdd(&asum[b * KK + tid], sAcc[tid]);
}

// ---------------- kernel 2: tf32 warp-MMA GEMM + fused residual epilogue -----
// grid (B, 4): CTA = batch b, 128 d-cols. 8 warps: wk = wid&1 (32 k-rows),
// wd = wid>>2.. -> 2(k) x 4(d), warp tile 32k x 32d. Chunk = 16 n.
#define PS 20
#define XS 136
__global__ void __launch_bounds__(256) k_gemm(const float* __restrict__ Pt,
                                              const float* __restrict__ xg,
                                              const float* __restrict__ c2t,
                                              const float* __restrict__ asum,
                                              float* __restrict__ vlad,
                                              float* __restrict__ ss) {
    __shared__ __align__(16) uint32_t sP[2][64][PS];
    __shared__ __align__(16) uint32_t sX[2][16][XS];
    const int tid = threadIdx.x;
    const int wid = tid >> 5, lane = tid & 31;
    const int gid = lane >> 2, tid4 = lane & 3;
    const int wk = wid & 1, wd = wid >> 1;
    const int b = blockIdx.x;
    const int d0 = blockIdx.y * 128;
    const float* Pb = Pt + (size_t)b * KK * NN;
    const float* Xb = xg + (size_t)b * NN * DD;

    float acc[2][4][4];
#pragma unroll
    for (int i = 0; i < 2; i++)
#pragma unroll
        for (int j = 0; j < 4; j++)
#pragma unroll
            for (int l = 0; l < 4; l++) acc[i][j][l] = 0.f;

    const int pk = tid >> 2, pnq = tid & 3;      // P fill: row, quad
    float4 pP;
    float4 pX[2];
    pP = *(const float4*)&Pb[(size_t)pk * NN + pnq * 4];
#pragma unroll
    for (int rep = 0; rep < 2; rep++) {
        int f = rep * 256 + tid;
        int row = f >> 5, dq = f & 31;
        pX[rep] = *(const float4*)&Xb[(size_t)row * DD + d0 + dq * 4];
    }

    for (int s = 0; s < 64; ++s) {
        int bf = s & 1;
        {   // store prefetched chunk (convert to tf32 once here)
            uint4 up;
            up.x = tf32cvt(pP.x); up.y = tf32cvt(pP.y);
            up.z = tf32cvt(pP.z); up.w = tf32cvt(pP.w);
            *(uint4*)&sP[bf][pk][pnq * 4] = up;
#pragma unroll
            for (int rep = 0; rep < 2; rep++) {
                int f = rep * 256 + tid;
                int row = f >> 5, dq = f & 31;
                uint4 ux;
                ux.x = tf32cvt(pX[rep].x); ux.y = tf32cvt(pX[rep].y);
                ux.z = tf32cvt(pX[rep].z); ux.w = tf32cvt(pX[rep].w);
                *(uint4*)&sX[bf][row][dq * 4] = ux;
            }
        }
        __syncthreads();
        if (s + 1 < 64) {
            int n0 = (s + 1) * 16;
            pP = *(const float4*)&Pb[(size_t)pk * NN + n0 + pnq * 4];
#pragma unroll
            for (int rep = 0; rep < 2; rep++) {
                int f = rep * 256 + tid;
                int row = f >> 5, dq = f & 31;
                pX[rep] = *(const float4*)&Xb[(size_t)(n0 + row) * DD + d0 + dq * 4];
            }
        }
#pragma unroll
        for (int ks = 0; ks < 2; ++ks) {
            int nb = ks * 8;
            uint32_t a[2][4], bfr[4][2];
#pragma unroll
            for (int mf = 0; mf < 2; mf++) {
                int r0 = wk * 32 + mf * 16 + gid;
                a[mf][0] = sP[bf][r0][nb + tid4];
                a[mf][1] = sP[bf][r0 + 8][nb + tid4];
                a[mf][2] = sP[bf][r0][nb + tid4 + 4];
                a[mf][3] = sP[bf][r0 + 8][nb + tid4 + 4];
            }
#pragma unroll
            for (int nf = 0; nf < 4; nf++) {
                int dc = wd * 32 + nf * 8 + gid;
                bfr[nf][0] = sX[bf][nb + tid4][dc];
                bfr[nf][1] = sX[bf][nb + tid4 + 4][dc];
            }
#pragma unroll
            for (int mf = 0; mf < 2; mf++)
#pragma unroll
                for (int nf = 0; nf < 4; nf++) mma_tf32(acc[mf][nf], a[mf], bfr[nf]);
        }
    }

    // ---- fused epilogue: v = acc - a_sum*c2, store residual, sumsq ----------
#pragma unroll
    for (int mf = 0; mf < 2; mf++) {
        int k0 = wk * 32 + mf * 16 + gid;          // low row
        float a_lo = asum[b * KK + k0];
        float a_hi = asum[b * KK + k0 + 8];
        float p_lo = 0.f, p_hi = 0.f;
#pragma unroll
        for (int nf = 0; nf < 4; nf++) {
            int d = d0 + wd * 32 + nf * 8 + tid4 * 2;
            float2 c2lo = *(const float2*)&c2t[(size_t)k0 * DD + d];
            float2 c2hi = *(const float2*)&c2t[(size_t)(k0 + 8) * DD + d];
            float v0 = acc[mf][nf][0] - a_lo * c2lo.x;
            float v1 = acc[mf][nf][1] - a_lo * c2lo.y;
            float v2 = acc[mf][nf][2] - a_hi * c2hi.x;
            float v3 = acc[mf][nf][3] - a_hi * c2hi.y;
            *(float2*)&vlad[((size_t)(b * KK + k0)) * DD + d] = make_float2(v0, v1);
            *(float2*)&vlad[((size_t)(b * KK + k0 + 8)) * DD + d] = make_float2(v2, v3);
            p_lo += v0 * v0 + v1 * v1;
            p_hi += v2 * v2 + v3 * v3;
        }
        // reduce over the 4 lanes of the quad (tid4 = low 2 bits)
        p_lo += __shfl_xor_sync(0xffffffffu, p_lo, 1);
        p_lo += __shfl_xor_sync(0xffffffffu, p_lo, 2);
        p_hi += __shfl_xor_sync(0xffffffffu, p_hi, 1);
        p_hi += __shfl_xor_sync(0xffffffffu, p_hi, 2);
        if (tid4 == 0) {
            atomicAdd(&ss[b * KK + k0], p_lo);
            atomicAdd(&ss[b * KK + k0 + 8], p_hi);
        }
    }
}

// ---------------- kernel 3: per-(b,k) scale + per-b global scale -------------
__global__ void k_rs(const float* __restrict__ ss, float* __restrict__ rs,
                     float* __restrict__ gn) {
    int b = blockIdx.x, t = threadIdx.x;    // 64 threads
    float s = ss[b * KK + t];
    float r = rsqrtf(s + EPSF);
    rs[b * KK + t] = r;
    float v = s * r * r;
#pragma unroll
    for (int o = 16; o; o >>= 1) v += __shfl_xor_sync(0xffffffffu, v, o);
    __shared__ float sh[2];
    if ((t & 31) == 0) sh[t >> 5] = v;
    __syncthreads();
    if (t == 0) gn[b] = rsqrtf(sh[0] + sh[1] + EPSF);
}

// ---------------- kernel 4: scale + transpose [B,K,D] -> [B, D*K] ------------
__global__ void k_final(const float* __restrict__ vlad,
                        const float* __restrict__ rs,
                        const float* __restrict__ gn,
                        float* __restrict__ out) {
    int b = blockIdx.x, dt = blockIdx.y, kt = blockIdx.z;
    __shared__ float t[32][33];
    int tx = threadIdx.x, ty = threadIdx.y;
    float g = gn[b];
#pragma unroll
    for (int r = 0; r < 4; r++) {
        int kl = ty + 8 * r;
        int k = kt * 32 + kl;
        int d = dt * 32 + tx;
        int bk = b * KK + k;
        t[kl][tx] = vlad[(size_t)bk * DD + d] * rs[bk];
    }
    __syncthreads();
#pragma unroll
    for (int r = 0; r < 4; r++) {
        int dl = ty + 8 * r;
        int d = dt * 32 + dl;
        int k = kt * 32 + tx;
        out[(size_t)b * (DD * KK) + d * KK + k] = t[tx][dl] * g;
    }
}

// ---------------- launcher ---------------------------------------------------
extern "C" void kernel_launch(void* const* d_in, const int* in_sizes, int n_in,
                              void* d_out, int out_size) {
    const float* x = (const float*)d_in[0];     // [B,N,D]
    const float* bn = (const float*)d_in[1];    // [B*N,K]
    const float* c2 = (const float*)d_in[2];    // [1,D,K]
    float* out = (float*)d_out;

    float *Pt, *vlad, *asum, *ssp, *rs, *gn, *c2t;
    cudaGetSymbolAddress((void**)&Pt, g_Pt);
    cudaGetSymbolAddress((void**)&vlad, g_vlad);
    cudaGetSymbolAddress((void**)&asum, g_asum);
    cudaGetSymbolAddress((void**)&ssp, g_ss);
    cudaGetSymbolAddress((void**)&rs, g_rs);
    cudaGetSymbolAddress((void**)&gn, g_gn);
    cudaGetSymbolAddress((void**)&c2t, g_c2t);

    cudaMemsetAsync(asum, 0, BB * KK * sizeof(float));                 // 0
    cudaMemsetAsync(ssp, 0, BB * KK * sizeof(float));                  // 1
    k_tc2<<<dim3(DD / 32, KK / 32), dim3(32, 8)>>>(c2, c2t);           // 2
    k_softmax<<<(BB * NN) / 32, 256>>>(bn, Pt, asum);                  // 3
    k_tc2<<<dim3(DD / 32, KK / 32), dim3(32, 8)>>>(c2, c2t);           // 4 (aligns ncu -s 5 on k_gemm)
    k_gemm<<<dim3(BB, DD / 128), 256>>>(Pt, x, c2t, asum, vlad, ssp);  // 5
    k_rs<<<BB, 64>>>(ssp, rs, gn);                                     // 6
    k_final<<<dim3(BB, DD / 32, KK / 32), dim3(32, 8)>>>(vlad, rs, gn, out); // 7
}

// round 6
// speedup vs baseline: 2.7855x; 1.6145x over previous
#include <cuda_runtime.h>
#include <cstdint>

#define BB 32
#define NN 1024
#define DD 512
#define KK 64
#define EPSF 1e-12f

// ---------------- scratch ----------------------------------------------------
__device__ float g_Pt[BB * KK * NN];       // P transposed [B,K,N]
__device__ float g_vlad[BB * KK * DD];     // residual vlad' [B,K,D]
__device__ float g_asum[BB * KK];
__device__ float g_ss[BB * KK];            // per-(b,k) sumsq of residual
__device__ float g_rs[BB * KK];
__device__ float g_gn[BB];
__device__ float g_c2t[KK * DD];

// ---------------- helpers ----------------------------------------------------
__device__ __forceinline__ uint32_t smem_u32(const void* p) {
    uint32_t a;
    asm("{ .reg .u64 t; cvta.to.shared.u64 t, %1; cvt.u32.u64 %0, t; }" : "=r"(a) : "l"(p));
    return a;
}
__device__ __forceinline__ void cpa16(uint32_t s, const void* g) {
    asm volatile("cp.async.cg.shared.global [%0], [%1], 16;" :: "r"(s), "l"(g));
}
__device__ __forceinline__ void mma_tf32(float* c, const uint32_t* a, const uint32_t* b) {
    asm volatile(
        "mma.sync.aligned.m16n8k8.row.col.f32.tf32.tf32.f32 "
        "{%0,%1,%2,%3}, {%4,%5,%6,%7}, {%8,%9}, {%0,%1,%2,%3};"
        : "+f"(c[0]), "+f"(c[1]), "+f"(c[2]), "+f"(c[3])
        : "r"(a[0]), "r"(a[1]), "r"(a[2]), "r"(a[3]), "r"(b[0]), "r"(b[1]));
}

// ---------------- kernel 0: transpose c2 [D,K] -> c2t [K,D] ------------------
__global__ void k_tc2(const float* __restrict__ c2, float* __restrict__ c2t) {
    __shared__ float t[32][33];
    int dt = blockIdx.x, kt = blockIdx.y;
    int tx = threadIdx.x, ty = threadIdx.y;
#pragma unroll
    for (int r = 0; r < 4; r++)
        t[ty + 8 * r][tx] = c2[(dt * 32 + ty + 8 * r) * KK + kt * 32 + tx];
    __syncthreads();
#pragma unroll
    for (int r = 0; r < 4; r++)
        c2t[(kt * 32 + ty + 8 * r) * DD + dt * 32 + tx] = t[tx][ty + 8 * r];
}

// ---------------- kernel 1: softmax over K, write Pt [B,K,N], a_sum ----------
__global__ void __launch_bounds__(256) k_softmax(const float* __restrict__ bn,
                                                 float* __restrict__ Pt,
                                                 float* __restrict__ asum) {
    __shared__ float sp[32][65];
    __shared__ float sAcc[KK];
    int tid = threadIdx.x;
    int w = tid >> 5, lane = tid & 31;
    int blk = blockIdx.x;
    int b = blk >> 5;
    int n0 = (blk & 31) * 32;
    if (tid < KK) sAcc[tid] = 0.f;
    __syncthreads();

#pragma unroll
    for (int r = 0; r < 4; r++) {
        int nl = w * 4 + r;
        const float* row = bn + ((size_t)(b * NN + n0 + nl)) * KK;
        float v0 = row[lane], v1 = row[lane + 32];
        float m = fmaxf(v0, v1);
#pragma unroll
        for (int o = 16; o; o >>= 1) m = fmaxf(m, __shfl_xor_sync(0xffffffffu, m, o));
        float e0 = __expf(v0 - m), e1 = __expf(v1 - m);
        float s = e0 + e1;
#pragma unroll
        for (int o = 16; o; o >>= 1) s += __shfl_xor_sync(0xffffffffu, s, o);
        float inv = 1.f / s;
        float p0 = e0 * inv, p1 = e1 * inv;
        sp[nl][lane] = p0;
        sp[nl][lane + 32] = p1;
        atomicAdd(&sAcc[lane], p0);
        atomicAdd(&sAcc[lane + 32], p1);
    }
    __syncthreads();
#pragma unroll
    for (int rep = 0; rep < 8; rep++) {
        int k = rep * 8 + w;
        Pt[((size_t)(b * KK + k)) * NN + n0 + lane] = sp[lane][k];
    }
    if (tid < KK) atomicAdd(&asum[b * KK + tid], sAcc[tid]);
}

// ---------------- kernel 2: tf32 warp-MMA GEMM, cp.async 4-stage -------------
// grid (B, 8): CTA = batch b, 64 d-cols, full N. 8 warps = 2(k:32) x 4(d:16).
// chunk = 16 n; stages = 4; raw fp32 bits fed to mma.tf32 (HW truncation).
#define PS 20
#define XS 72
#define PSTG (64 * PS * 4)      // 5120 B per stage
#define XSTG (16 * XS * 4)      // 4608 B per stage
__global__ void __launch_bounds__(256) k_gemm(const float* __restrict__ Pt,
                                              const float* __restrict__ xg,
                                              const float* __restrict__ c2t,
                                              const float* __restrict__ asum,
                                              float* __restrict__ vlad,
                                              float* __restrict__ ss) {
    __shared__ __align__(16) uint32_t sP[4][64][PS];
    __shared__ __align__(16) uint32_t sX[4][16][XS];
    const int tid = threadIdx.x;
    const int wid = tid >> 5, lane = tid & 31;
    const int gid = lane >> 2, tid4 = lane & 3;
    const int wk = wid & 1, wd = wid >> 1;
    const int b = blockIdx.x;
    const int d0 = blockIdx.y * 64;
    const float* Pb = Pt + (size_t)b * KK * NN;
    const float* Xb = xg + (size_t)b * NN * DD;

    float acc[2][2][4];
#pragma unroll
    for (int i = 0; i < 2; i++)
#pragma unroll
        for (int j = 0; j < 2; j++)
#pragma unroll
            for (int l = 0; l < 4; l++) acc[i][j][l] = 0.f;

    // cp.async source/dest bases for this thread
    const int pk = tid >> 2, pnq = tid & 3;    // P: 64 rows x 4 quads
    const int xr = tid >> 4, xdq = tid & 15;   // X: 16 rows x 16 quads
    const uint32_t pDst0 = smem_u32(&sP[0][0][0]) + pk * (PS * 4) + pnq * 16;
    const uint32_t xDst0 = smem_u32(&sX[0][0][0]) + xr * (XS * 4) + xdq * 16;
    const float* pSrc0 = Pb + (size_t)pk * NN + pnq * 4;
    const float* xSrc0 = Xb + (size_t)xr * DD + d0 + xdq * 4;

#define ISSUE(st, s)                                                    \
    do {                                                                \
        cpa16(pDst0 + (st) * PSTG, pSrc0 + (s) * 16);                   \
        cpa16(xDst0 + (st) * XSTG, xSrc0 + (size_t)(s) * 16 * DD);      \
        asm volatile("cp.async.commit_group;");                         \
    } while (0)

    ISSUE(0, 0);
    ISSUE(1, 1);
    ISSUE(2, 2);

    for (int s = 0; s < 64; ++s) {
        int st = s & 3;
        asm volatile("cp.async.wait_group 2;");
        __syncthreads();
        if (s + 3 < 64) {
            int ns = s + 3;
            ISSUE(ns & 3, ns);
        } else {
            asm volatile("cp.async.commit_group;");
        }
#pragma unroll
        for (int ks = 0; ks < 2; ++ks) {
            int nb = ks * 8;
            uint32_t a[2][4], bf2[2][2];
#pragma unroll
            for (int mf = 0; mf < 2; mf++) {
                int r0 = wk * 32 + mf * 16 + gid;
                a[mf][0] = sP[st][r0][nb + tid4];
                a[mf][1] = sP[st][r0 + 8][nb + tid4];
                a[mf][2] = sP[st][r0][nb + tid4 + 4];
                a[mf][3] = sP[st][r0 + 8][nb + tid4 + 4];
            }
#pragma unroll
            for (int nf = 0; nf < 2; nf++) {
                int dc = wd * 16 + nf * 8 + gid;
                bf2[nf][0] = sX[st][nb + tid4][dc];
                bf2[nf][1] = sX[st][nb + tid4 + 4][dc];
            }
#pragma unroll
            for (int mf = 0; mf < 2; mf++)
#pragma unroll
                for (int nf = 0; nf < 2; nf++) mma_tf32(acc[mf][nf], a[mf], bf2[nf]);
        }
    }
#undef ISSUE

    // ---- fused epilogue: v = acc - a_sum*c2, store residual, sumsq ----------
#pragma unroll
    for (int mf = 0; mf < 2; mf++) {
        int k0 = wk * 32 + mf * 16 + gid;
        float a_lo = asum[b * KK + k0];
        float a_hi = asum[b * KK + k0 + 8];
        float p_lo = 0.f, p_hi = 0.f;
#pragma unroll
        for (int nf = 0; nf < 2; nf++) {
            int d = d0 + wd * 16 + nf * 8 + tid4 * 2;
            float2 c2lo = *(const float2*)&c2t[(size_t)k0 * DD + d];
            float2 c2hi = *(const float2*)&c2t[(size_t)(k0 + 8) * DD + d];
            float v0 = acc[mf][nf][0] - a_lo * c2lo.x;
            float v1 = acc[mf][nf][1] - a_lo * c2lo.y;
            float v2 = acc[mf][nf][2] - a_hi * c2hi.x;
            float v3 = acc[mf][nf][3] - a_hi * c2hi.y;
            *(float2*)&vlad[((size_t)(b * KK + k0)) * DD + d] = make_float2(v0, v1);
            *(float2*)&vlad[((size_t)(b * KK + k0 + 8)) * DD + d] = make_float2(v2, v3);
            p_lo += v0 * v0 + v1 * v1;
            p_hi += v2 * v2 + v3 * v3;
        }
        p_lo += __shfl_xor_sync(0xffffffffu, p_lo, 1);
        p_lo += __shfl_xor_sync(0xffffffffu, p_lo, 2);
        p_hi += __shfl_xor_sync(0xffffffffu, p_hi, 1);
        p_hi += __shfl_xor_sync(0xffffffffu, p_hi, 2);
        if (tid4 == 0) {
            atomicAdd(&ss[b * KK + k0], p_lo);
            atomicAdd(&ss[b * KK + k0 + 8], p_hi);
        }
    }
}

// ---------------- kernel 3: per-(b,k) scale + per-b global scale -------------
__global__ void k_rs(const float* __restrict__ ss, float* __restrict__ rs,
                     float* __restrict__ gn) {
    int b = blockIdx.x, t = threadIdx.x;    // 64 threads
    float s = ss[b * KK + t];
    float r = rsqrtf(s + EPSF);
    rs[b * KK + t] = r;
    float v = s * r * r;
#pragma unroll
    for (int o = 16; o; o >>= 1) v += __shfl_xor_sync(0xffffffffu, v, o);
    __shared__ float sh[2];
    if ((t & 31) == 0) sh[t >> 5] = v;
    __syncthreads();
    if (t == 0) gn[b] = rsqrtf(sh[0] + sh[1] + EPSF);
}

// ---------------- kernel 4: scale + transpose [B,K,D] -> [B, D*K] ------------
__global__ void k_final(const float* __restrict__ vlad,
                        const float* __restrict__ rs,
                        const float* __restrict__ gn,
                        float* __restrict__ out) {
    int b = blockIdx.x, dt = blockIdx.y, kt = blockIdx.z;
    __shared__ float t[32][33];
    int tx = threadIdx.x, ty = threadIdx.y;
    float g = gn[b];
#pragma unroll
    for (int r = 0; r < 4; r++) {
        int kl = ty + 8 * r;
        int k = kt * 32 + kl;
        int d = dt * 32 + tx;
        int bk = b * KK + k;
        t[kl][tx] = vlad[(size_t)bk * DD + d] * rs[bk];
    }
    __syncthreads();
#pragma unroll
    for (int r = 0; r < 4; r++) {
        int dl = ty + 8 * r;
        int d = dt * 32 + dl;
        int k = kt * 32 + tx;
        out[(size_t)b * (DD * KK) + d * KK + k] = t[tx][dl] * g;
    }
}

// ---------------- launcher ---------------------------------------------------
extern "C" void kernel_launch(void* const* d_in, const int* in_sizes, int n_in,
                              void* d_out, int out_size) {
    const float* x = (const float*)d_in[0];     // [B,N,D]
    const float* bn = (const float*)d_in[1];    // [B*N,K]
    const float* c2 = (const float*)d_in[2];    // [1,D,K]
    float* out = (float*)d_out;

    float *Pt, *vlad, *asum, *ssp, *rs, *gn, *c2t;
    cudaGetSymbolAddress((void**)&Pt, g_Pt);
    cudaGetSymbolAddress((void**)&vlad, g_vlad);
    cudaGetSymbolAddress((void**)&asum, g_asum);
    cudaGetSymbolAddress((void**)&ssp, g_ss);
    cudaGetSymbolAddress((void**)&rs, g_rs);
    cudaGetSymbolAddress((void**)&gn, g_gn);
    cudaGetSymbolAddress((void**)&c2t, g_c2t);

    cudaMemsetAsync(asum, 0, BB * KK * sizeof(float));                 // 0
    cudaMemsetAsync(ssp, 0, BB * KK * sizeof(float));                  // 1
    k_tc2<<<dim3(DD / 32, KK / 32), dim3(32, 8)>>>(c2, c2t);           // 2
    k_softmax<<<(BB * NN) / 32, 256>>>(bn, Pt, asum);                  // 3
    k_tc2<<<dim3(DD / 32, KK / 32), dim3(32, 8)>>>(c2, c2t);           // 4 (aligns ncu -s 5 on k_gemm)
    k_gemm<<<dim3(BB, DD / 64), 256>>>(Pt, x, c2t, asum, vlad, ssp);   // 5
    k_rs<<<BB, 64>>>(ssp, rs, gn);                                     // 6
    k_final<<<dim3(BB, DD / 32, KK / 32), dim3(32, 8)>>>(vlad, rs, gn, out); // 7
}

// round 9
// speedup vs baseline: 3.4465x; 1.2373x over previous
#include <cuda_runtime.h>
#include <cuda_fp16.h>
#include <cstdint>
#include <cstring>

#define BB 32
#define NN 1024
#define DD 512
#define KK 64
#define EPSF 1e-12f

// ---------------- scratch ----------------------------------------------------
__device__ __half g_Pth[BB * KK * NN];     // P transposed [B,K,N] fp16
__device__ float g_vlad[BB * KK * DD];     // residual vlad' [B,K,D]
__device__ float g_asum[BB * KK];
__device__ float g_ss[BB * KK];
__device__ float g_rs[BB * KK];
__device__ float g_gn[BB];
__device__ float g_c2t[KK * DD];

// ---------------- helpers ----------------------------------------------------
__device__ __forceinline__ uint32_t h2u(__half2 h) {
    uint32_t u;
    memcpy(&u, &h, 4);
    return u;
}
__device__ __forceinline__ uint32_t smem_u32(const void* p) {
    uint32_t a;
    asm("{ .reg .u64 t; cvta.to.shared.u64 t, %1; cvt.u32.u64 %0, t; }" : "=r"(a) : "l"(p));
    return a;
}
__device__ __forceinline__ void cpa16(uint32_t s, const void* g) {
    asm volatile("cp.async.cg.shared.global [%0], [%1], 16;" :: "r"(s), "l"(g));
}
__device__ __forceinline__ void ldsm4(uint32_t* r, uint32_t a) {
    asm volatile("ldmatrix.sync.aligned.m8n8.x4.shared.b16 {%0,%1,%2,%3}, [%4];"
                 : "=r"(r[0]), "=r"(r[1]), "=r"(r[2]), "=r"(r[3]) : "r"(a));
}
__device__ __forceinline__ void ldsm2t(uint32_t* r, uint32_t a) {
    asm volatile("ldmatrix.sync.aligned.m8n8.x2.trans.shared.b16 {%0,%1}, [%2];"
                 : "=r"(r[0]), "=r"(r[1]) : "r"(a));
}
__device__ __forceinline__ void mma16816(float* c, const uint32_t* a, const uint32_t* b) {
    asm volatile(
        "mma.sync.aligned.m16n8k16.row.col.f32.f16.f16.f32 "
        "{%0,%1,%2,%3}, {%4,%5,%6,%7}, {%8,%9}, {%0,%1,%2,%3};"
        : "+f"(c[0]), "+f"(c[1]), "+f"(c[2]), "+f"(c[3])
        : "r"(a[0]), "r"(a[1]), "r"(a[2]), "r"(a[3]), "r"(b[0]), "r"(b[1]));
}

// ---------------- kernel 0: transpose c2 [D,K] -> c2t [K,D] ------------------
__global__ void k_tc2(const float* __restrict__ c2, float* __restrict__ c2t) {
    __shared__ float t[32][33];
    int dt = blockIdx.x, kt = blockIdx.y;
    int tx = threadIdx.x, ty = threadIdx.y;
#pragma unroll
    for (int r = 0; r < 4; r++)
        t[ty + 8 * r][tx] = c2[(dt * 32 + ty + 8 * r) * KK + kt * 32 + tx];
    __syncthreads();
#pragma unroll
    for (int r = 0; r < 4; r++)
        c2t[(kt * 32 + ty + 8 * r) * DD + dt * 32 + tx] = t[tx][ty + 8 * r];
}

// ---------------- kernel 1: softmax over K -> Pt (fp16), a_sum (fp32) --------
__global__ void __launch_bounds__(256) k_softmax(const float* __restrict__ bn,
                                                 __half* __restrict__ Pt,
                                                 float* __restrict__ asum) {
    __shared__ float sp[32][65];
    __shared__ float sAcc[KK];
    int tid = threadIdx.x;
    int w = tid >> 5, lane = tid & 31;
    int blk = blockIdx.x;
    int b = blk >> 5;
    int n0 = (blk & 31) * 32;
    if (tid < KK) sAcc[tid] = 0.f;
    __syncthreads();

#pragma unroll
    for (int r = 0; r < 4; r++) {
        int nl = w * 4 + r;
        const float* row = bn + ((size_t)(b * NN + n0 + nl)) * KK;
        float v0 = row[lane], v1 = row[lane + 32];
        float m = fmaxf(v0, v1);
#pragma unroll
        for (int o = 16; o; o >>= 1) m = fmaxf(m, __shfl_xor_sync(0xffffffffu, m, o));
        float e0 = __expf(v0 - m), e1 = __expf(v1 - m);
        float s = e0 + e1;
#pragma unroll
        for (int o = 16; o; o >>= 1) s += __shfl_xor_sync(0xffffffffu, s, o);
        float inv = 1.f / s;
        float p0 = e0 * inv, p1 = e1 * inv;
        sp[nl][lane] = p0;
        sp[nl][lane + 32] = p1;
        atomicAdd(&sAcc[lane], p0);
        atomicAdd(&sAcc[lane + 32], p1);
    }
    __syncthreads();
#pragma unroll
    for (int rep = 0; rep < 8; rep++) {
        int k = rep * 8 + w;
        Pt[((size_t)(b * KK + k)) * NN + n0 + lane] = __float2half_rn(sp[lane][k]);
    }
    if (tid < KK) atomicAdd(&asum[b * KK + tid], sAcc[tid]);
}

// ---------------- kernel 2: fp16 warp-MMA GEMM (ldmatrix), fused epilogue ----
// grid (B, 8): CTA = batch b, 64 d. 8 warps = 2(k:32) x 4(d:16). chunk = 32 n.
// P (half) via 4-stage cp.async; X (fp32) via LDG->cvt->STS, 2-deep reg buffer.
#define PPAD 40
#define XPAD 72
#define PSTGB (64 * PPAD * 2)   // 5120 B
__global__ void __launch_bounds__(256) k_gemm(const __half* __restrict__ Pt,
                                              const float* __restrict__ xg,
                                              const float* __restrict__ c2t,
                                              const float* __restrict__ asum,
                                              float* __restrict__ vlad,
                                              float* __restrict__ ss) {
    __shared__ __align__(16) __half sPh[4][64][PPAD];
    __shared__ __align__(16) __half sXh[2][32][XPAD];
    const int tid = threadIdx.x;
    const int wid = tid >> 5, lane = tid & 31;
    const int gid = lane >> 2, tid4 = lane & 3;
    const int wk = wid & 1, wd = wid >> 1;
    const int b = blockIdx.x;
    const int d0 = blockIdx.y * 64;
    const __half* Pb = Pt + (size_t)b * KK * NN;
    const float* Xb = xg + (size_t)b * NN * DD + d0;

    float acc[2][2][4];
#pragma unroll
    for (int i = 0; i < 2; i++)
#pragma unroll
        for (int j = 0; j < 2; j++)
#pragma unroll
            for (int l = 0; l < 4; l++) acc[i][j][l] = 0.f;

    // P cp.async map: 256 thr -> 64 rows x 4 segs of 8 halves (16B)
    const int pr = tid >> 2, pseg = tid & 3;
    const __half* pSrc = Pb + (size_t)pr * NN + pseg * 8;
    const uint32_t pDst = smem_u32(&sPh[0][pr][pseg * 8]);
    // X map: 256 thr -> 32 rows x 8 groups of 8 floats
    const int xr = tid >> 3, xq = tid & 7;
    const float* xSrc = Xb + (size_t)xr * DD + xq * 8;

#pragma unroll
    for (int s = 0; s < 3; s++) {
        cpa16(pDst + s * PSTGB, pSrc + s * 32);
        asm volatile("cp.async.commit_group;");
    }
    float4 xa[2], xb[2];
    xa[0] = *(const float4*)(xSrc);
    xb[0] = *(const float4*)(xSrc + 4);
    xa[1] = *(const float4*)(xSrc + (size_t)32 * DD);
    xb[1] = *(const float4*)(xSrc + (size_t)32 * DD + 4);

    for (int s = 0; s < 32; ++s) {
        const int sl = s & 1, st = s & 3;
        {   // STS X(s): fp32 regs -> fp16 smem (16B store)
            uint4 u;
            u.x = h2u(__floats2half2_rn(xa[sl].x, xa[sl].y));
            u.y = h2u(__floats2half2_rn(xa[sl].z, xa[sl].w));
            u.z = h2u(__floats2half2_rn(xb[sl].x, xb[sl].y));
            u.w = h2u(__floats2half2_rn(xb[sl].z, xb[sl].w));
            *(uint4*)&sXh[sl][xr][xq * 8] = u;
        }
        asm volatile("cp.async.wait_group 2;");
        __syncthreads();
        if (s + 2 < 32) {
            const float* src = xSrc + (size_t)(s + 2) * 32 * DD;
            xa[sl] = *(const float4*)(src);
            xb[sl] = *(const float4*)(src + 4);
        }
        if (s + 3 < 32) {
            cpa16(pDst + ((s + 3) & 3) * PSTGB, pSrc + (s + 3) * 32);
            asm volatile("cp.async.commit_group;");
        }
#pragma unroll
        for (int ks = 0; ks < 2; ++ks) {
            uint32_t a[2][4], bf[2][2];
#pragma unroll
            for (int mf = 0; mf < 2; mf++) {
                uint32_t aaddr = smem_u32(
                    &sPh[st][wk * 32 + mf * 16 + (lane & 15)][ks * 16 + ((lane >> 4) << 3)]);
                ldsm4(a[mf], aaddr);
            }
#pragma unroll
            for (int nf = 0; nf < 2; nf++) {
                uint32_t baddr = smem_u32(
                    &sXh[sl][ks * 16 + (lane & 15)][wd * 16 + nf * 8]);
                ldsm2t(bf[nf], baddr);
            }
#pragma unroll
            for (int mf = 0; mf < 2; mf++)
#pragma unroll
                for (int nf = 0; nf < 2; nf++) mma16816(acc[mf][nf], a[mf], bf[nf]);
        }
    }

    // ---- fused epilogue: v = acc - a_sum*c2, store residual, sumsq ----------
#pragma unroll
    for (int mf = 0; mf < 2; mf++) {
        int k0 = wk * 32 + mf * 16 + gid;
        float a_lo = asum[b * KK + k0];
        float a_hi = asum[b * KK + k0 + 8];
        float p_lo = 0.f, p_hi = 0.f;
#pragma unroll
        for (int nf = 0; nf < 2; nf++) {
            int d = d0 + wd * 16 + nf * 8 + tid4 * 2;
            float2 c2lo = *(const float2*)&c2t[(size_t)k0 * DD + d];
            float2 c2hi = *(const float2*)&c2t[(size_t)(k0 + 8) * DD + d];
            float v0 = acc[mf][nf][0] - a_lo * c2lo.x;
            float v1 = acc[mf][nf][1] - a_lo * c2lo.y;
            float v2 = acc[mf][nf][2] - a_hi * c2hi.x;
            float v3 = acc[mf][nf][3] - a_hi * c2hi.y;
            *(float2*)&vlad[((size_t)(b * KK + k0)) * DD + d] = make_float2(v0, v1);
            *(float2*)&vlad[((size_t)(b * KK + k0 + 8)) * DD + d] = make_float2(v2, v3);
            p_lo += v0 * v0 + v1 * v1;
            p_hi += v2 * v2 + v3 * v3;
        }
        p_lo += __shfl_xor_sync(0xffffffffu, p_lo, 1);
        p_lo += __shfl_xor_sync(0xffffffffu, p_lo, 2);
        p_hi += __shfl_xor_sync(0xffffffffu, p_hi, 1);
        p_hi += __shfl_xor_sync(0xffffffffu, p_hi, 2);
        if (tid4 == 0) {
            atomicAdd(&ss[b * KK + k0], p_lo);
            atomicAdd(&ss[b * KK + k0 + 8], p_hi);
        }
    }
}

// ---------------- kernel 3: per-(b,k) scale + per-b global scale -------------
__global__ void k_rs(const float* __restrict__ ss, float* __restrict__ rs,
                     float* __restrict__ gn) {
    int b = blockIdx.x, t = threadIdx.x;    // 64 threads
    float s = ss[b * KK + t];
    float r = rsqrtf(s + EPSF);
    rs[b * KK + t] = r;
    float v = s * r * r;
#pragma unroll
    for (int o = 16; o; o >>= 1) v += __shfl_xor_sync(0xffffffffu, v, o);
    __shared__ float sh[2];
    if ((t & 31) == 0) sh[t >> 5] = v;
    __syncthreads();
    if (t == 0) gn[b] = rsqrtf(sh[0] + sh[1] + EPSF);
}

// ---------------- kernel 4: scale + transpose [B,K,D] -> [B, D*K] ------------
__global__ void k_final(const float* __restrict__ vlad,
                        const float* __restrict__ rs,
                        const float* __restrict__ gn,
                        float* __restrict__ out) {
    int b = blockIdx.x, dt = blockIdx.y, kt = blockIdx.z;
    __shared__ float t[32][33];
    int tx = threadIdx.x, ty = threadIdx.y;
    float g = gn[b];
#pragma unroll
    for (int r = 0; r < 4; r++) {
        int kl = ty + 8 * r;
        int k = kt * 32 + kl;
        int d = dt * 32 + tx;
        int bk = b * KK + k;
        t[kl][tx] = vlad[(size_t)bk * DD + d] * rs[bk];
    }
    __syncthreads();
#pragma unroll
    for (int r = 0; r < 4; r++) {
        int dl = ty + 8 * r;
        int d = dt * 32 + dl;
        int k = kt * 32 + tx;
        out[(size_t)b * (DD * KK) + d * KK + k] = t[tx][dl] * g;
    }
}

// ---------------- launcher ---------------------------------------------------
extern "C" void kernel_launch(void* const* d_in, const int* in_sizes, int n_in,
                              void* d_out, int out_size) {
    const float* x = (const float*)d_in[0];     // [B,N,D]
    const float* bn = (const float*)d_in[1];    // [B*N,K]
    const float* c2 = (const float*)d_in[2];    // [1,D,K]
    float* out = (float*)d_out;

    __half* Pth;
    float *vlad, *asum, *ssp, *rs, *gn, *c2t;
    cudaGetSymbolAddress((void**)&Pth, g_Pth);
    cudaGetSymbolAddress((void**)&vlad, g_vlad);
    cudaGetSymbolAddress((void**)&asum, g_asum);
    cudaGetSymbolAddress((void**)&ssp, g_ss);
    cudaGetSymbolAddress((void**)&rs, g_rs);
    cudaGetSymbolAddress((void**)&gn, g_gn);
    cudaGetSymbolAddress((void**)&c2t, g_c2t);

    cudaMemsetAsync(asum, 0, BB * KK * sizeof(float));                 // 0
    cudaMemsetAsync(ssp, 0, BB * KK * sizeof(float));                  // 1
    k_tc2<<<dim3(DD / 32, KK / 32), dim3(32, 8)>>>(c2, c2t);           // 2
    k_softmax<<<(BB * NN) / 32, 256>>>(bn, Pth, asum);                 // 3
    k_tc2<<<dim3(DD / 32, KK / 32), dim3(32, 8)>>>(c2, c2t);           // 4 (aligns ncu -s 5 on k_gemm)
    k_gemm<<<dim3(BB, DD / 64), 256>>>(Pth, x, c2t, asum, vlad, ssp);  // 5
    k_rs<<<BB, 64>>>(ssp, rs, gn);                                     // 6
    k_final<<<dim3(BB, DD / 32, KK / 32), dim3(32, 8)>>>(vlad, rs, gn, out); // 7
}